// round 1
// baseline (speedup 1.0000x reference)
#include <cuda_runtime.h>

#define T_ 3
#define H_ 4
#define DIN 64
#define FEAT_IN 192     /* T_*DIN */
#define FDIM 384        /* H_ * T_*32 */
#define EF_ 64
#define NET 5
#define MAXN 50000
#define MAXE 400000
#define NEG_SLOPE 0.2f

typedef unsigned long long ull;

__device__ float g_ft[(size_t)MAXN * FDIM];
__device__ float g_el[MAXN * H_];
__device__ float g_er[MAXN * H_];
__device__ float g_ee[32];
__device__ int   g_cnt[MAXN + 1];
__device__ int   g_off[MAXN + 1];
__device__ int   g_cur[MAXN + 1];
__device__ int   g_eidx[MAXE];

__device__ __forceinline__ ull pack2(float x, float y) {
    ull r; asm("mov.b64 %0, {%1,%2};" : "=l"(r) : "f"(x), "f"(y)); return r;
}
__device__ __forceinline__ ull fma2(ull a, ull b, ull c) {
    ull d; asm("fma.rn.f32x2 %0, %1, %2, %3;" : "=l"(d) : "l"(a), "l"(b), "l"(c)); return d;
}
__device__ __forceinline__ float lrelu(float x) { return x >= 0.f ? x : NEG_SLOPE * x; }
__device__ __forceinline__ float pick4(float4 v, int h) {
    float r = v.x;
    r = (h == 1) ? v.y : r;
    r = (h == 2) ? v.z : r;
    r = (h == 3) ? v.w : r;
    return r;
}

// ---------------------------------------------------------------------------
// CSR build
// ---------------------------------------------------------------------------
__global__ void k_zero(int N) {
    int i = blockIdx.x * blockDim.x + threadIdx.x;
    if (i <= N) g_cnt[i] = 0;
}

__global__ void k_count(const int* __restrict__ dst, int E) {
    int e = blockIdx.x * blockDim.x + threadIdx.x;
    if (e < E) atomicAdd(&g_cnt[dst[e]], 1);
}

__global__ void k_scan(int N) {
    __shared__ int wsum[32];
    __shared__ int carry;
    int tid = threadIdx.x;
    if (tid == 0) carry = 0;
    __syncthreads();
    for (int base = 0; base < N; base += 1024) {
        int i = base + tid;
        int x = (i < N) ? g_cnt[i] : 0;
        int incl = x;
#pragma unroll
        for (int d = 1; d < 32; d <<= 1) {
            int y = __shfl_up_sync(0xffffffffu, incl, d);
            if ((tid & 31) >= d) incl += y;
        }
        if ((tid & 31) == 31) wsum[tid >> 5] = incl;
        __syncthreads();
        if (tid < 32) {
            int s = wsum[tid];
#pragma unroll
            for (int d = 1; d < 32; d <<= 1) {
                int y = __shfl_up_sync(0xffffffffu, s, d);
                if (tid >= d) s += y;
            }
            wsum[tid] = s;
        }
        __syncthreads();
        int pre = carry + ((tid >= 32) ? wsum[(tid >> 5) - 1] : 0) + incl - x;
        if (i < N) { g_off[i] = pre; g_cur[i] = pre; }
        int tot = wsum[31];
        __syncthreads();
        if (tid == 0) carry += tot;
        __syncthreads();
    }
    if (tid == 0) g_off[N] = carry;
}

__global__ void k_scatter(const int* __restrict__ dst, int E) {
    int e = blockIdx.x * blockDim.x + threadIdx.x;
    if (e < E) {
        int p = atomicAdd(&g_cur[dst[e]], 1);
        g_eidx[p] = e;
    }
}

// ---------------------------------------------------------------------------
// ee table: ee[et][h] = sum_f attn_e[h,f] * (edge_emb[et] . fc_e_w[h*64+f, :])
// one warp per (et, h); deterministic
// ---------------------------------------------------------------------------
__global__ void k_ee(const float* __restrict__ emb, const float* __restrict__ fce,
                     const float* __restrict__ attn_e) {
    int w = threadIdx.x >> 5;
    int lane = threadIdx.x & 31;
    if (w >= NET * H_) return;
    int et = w / H_, h = w % H_;
    float acc = 0.f;
    for (int f = lane; f < EF_; f += 32) {
        const float* row = fce + (h * EF_ + f) * EF_;
        float inner = 0.f;
#pragma unroll 8
        for (int k = 0; k < EF_; k++) inner += emb[et * EF_ + k] * row[k];
        acc += inner * attn_e[h * EF_ + f];
    }
#pragma unroll
    for (int d = 16; d; d >>= 1) acc += __shfl_xor_sync(0xffffffffu, acc, d);
    if (lane == 0) g_ee[et * H_ + h] = acc;
}

// ---------------------------------------------------------------------------
// k1: node transform. ft -> g_ft, res -> out. f32x2 packed FMA, weights in SMEM.
// 256 threads: 64 column-pairs x 4 node-groups of 8 nodes = 32 nodes/tile.
// Persistent grid (weights loaded once per block).
// ---------------------------------------------------------------------------
#define K1_SMEM_FLOATS (2 * T_ * DIN * 128 + 32 * FEAT_IN)  /* 55296 */
__global__ void k1_transform(const float* __restrict__ feat, const float* __restrict__ fc,
                             const float* __restrict__ resw, float* __restrict__ out, int N) {
    extern __shared__ float sh[];
    float* wf = sh;
    float* wr = sh + T_ * DIN * 128;
    float* sf = sh + 2 * T_ * DIN * 128;
    for (int i = threadIdx.x; i < T_ * DIN * 128; i += blockDim.x) {
        wf[i] = fc[i];
        wr[i] = resw[i];
    }
    int c2 = threadIdx.x & 63;
    int grp = threadIdx.x >> 6;
    int j0 = c2 * 2;
    int hb = (j0 >> 5) * 96 + (j0 & 31);  // h*96 + o
    __syncthreads();

    for (int n0 = blockIdx.x * 32; n0 < N; n0 += gridDim.x * 32) {
        __syncthreads();
        int cnt = min(32, N - n0) * FEAT_IN;
        for (int i = threadIdx.x; i < cnt; i += blockDim.x)
            sf[i] = feat[(size_t)n0 * FEAT_IN + i];
        __syncthreads();
#pragma unroll
        for (int t = 0; t < T_; t++) {
            ull af[8], ar_[8];
#pragma unroll
            for (int i = 0; i < 8; i++) { af[i] = 0ull; ar_[i] = 0ull; }
            const float* wfp = wf + t * DIN * 128 + j0;
            const float* wrp = wr + t * DIN * 128 + j0;
            const float* fp = sf + (grp * 8) * FEAT_IN + t * DIN;
#pragma unroll 4
            for (int d = 0; d < DIN; d++) {
                ull w2f = *(const ull*)(wfp + d * 128);
                ull w2r = *(const ull*)(wrp + d * 128);
#pragma unroll
                for (int i = 0; i < 8; i++) {
                    float fv = fp[i * FEAT_IN + d];
                    ull f2 = pack2(fv, fv);
                    af[i] = fma2(f2, w2f, af[i]);
                    ar_[i] = fma2(f2, w2r, ar_[i]);
                }
            }
#pragma unroll
            for (int i = 0; i < 8; i++) {
                int n = n0 + grp * 8 + i;
                if (n < N) {
                    size_t idx = (size_t)n * FDIM + hb + t * 32;
                    *(ull*)(g_ft + idx) = af[i];
                    *(ull*)(out + idx) = ar_[i];
                }
            }
        }
    }
}

// ---------------------------------------------------------------------------
// k2: el/er per node. Warp per node, float4 chunks.
// ---------------------------------------------------------------------------
__global__ void k2_elr(const float* __restrict__ attn_l, const float* __restrict__ attn_r, int N) {
    int n = (blockIdx.x * blockDim.x + threadIdx.x) >> 5;
    int lane = threadIdx.x & 31;
    if (n >= N) return;
    const float4* f4 = (const float4*)(g_ft + (size_t)n * FDIM);
    float al[4] = {0, 0, 0, 0}, ar[4] = {0, 0, 0, 0};
#pragma unroll
    for (int c = 0; c < 3; c++) {
        int p = c * 128 + lane * 4;
        float4 fv = f4[c * 32 + lane];
        float4 a4 = *(const float4*)(attn_l + p);
        float4 b4 = *(const float4*)(attn_r + p);
        float dl = fv.x * a4.x + fv.y * a4.y + fv.z * a4.z + fv.w * a4.w;
        float dr = fv.x * b4.x + fv.y * b4.y + fv.z * b4.z + fv.w * b4.w;
        int h = p / 96;
#pragma unroll
        for (int hh = 0; hh < 4; hh++) {
            if (h == hh) { al[hh] += dl; ar[hh] += dr; }
        }
    }
#pragma unroll
    for (int hh = 0; hh < 4; hh++) {
#pragma unroll
        for (int d = 16; d; d >>= 1) {
            al[hh] += __shfl_xor_sync(0xffffffffu, al[hh], d);
            ar[hh] += __shfl_xor_sync(0xffffffffu, ar[hh], d);
        }
    }
    if (lane == 0) {
        *(float4*)(g_el + n * 4) = make_float4(al[0], al[1], al[2], al[3]);
        *(float4*)(g_er + n * 4) = make_float4(ar[0], ar[1], ar[2], ar[3]);
    }
}

// ---------------------------------------------------------------------------
// k7: softmax + aggregation. One warp per dst node.
// ---------------------------------------------------------------------------
__global__ void k7_agg(const int* __restrict__ src, const int* __restrict__ efeat,
                       float* __restrict__ out, int N) {
    int n = (blockIdx.x * blockDim.x + threadIdx.x) >> 5;
    int lane = threadIdx.x & 31;
    if (n >= N) return;
    int s0 = g_off[n];
    int deg = g_off[n + 1] - s0;
    if (deg == 0) return;

    float4 er4 = *(const float4*)(g_er + n * 4);

    float4 vc[4];
    int sc[4];
    float4 m = make_float4(-1e30f, -1e30f, -1e30f, -1e30f);
#pragma unroll
    for (int c = 0; c < 4; c++) {
        int k = lane + 32 * c;
        sc[c] = 0;
        vc[c] = make_float4(0.f, 0.f, 0.f, 0.f);
        if (k < deg) {
            int e = g_eidx[s0 + k];
            int s = src[e];
            int et = efeat[e];
            float4 l4 = *(const float4*)(g_el + s * 4);
            float4 e4 = *(const float4*)(g_ee + et * 4);
            float4 v;
            v.x = lrelu(l4.x + er4.x + e4.x);
            v.y = lrelu(l4.y + er4.y + e4.y);
            v.z = lrelu(l4.z + er4.z + e4.z);
            v.w = lrelu(l4.w + er4.w + e4.w);
            sc[c] = s;
            vc[c] = v;
            m.x = fmaxf(m.x, v.x); m.y = fmaxf(m.y, v.y);
            m.z = fmaxf(m.z, v.z); m.w = fmaxf(m.w, v.w);
        }
    }
    // tail (deg > 128), rare
    for (int k = lane + 128; k < deg; k += 32) {
        int e = g_eidx[s0 + k];
        int s = src[e];
        int et = efeat[e];
        float4 l4 = *(const float4*)(g_el + s * 4);
        float4 e4 = *(const float4*)(g_ee + et * 4);
        m.x = fmaxf(m.x, lrelu(l4.x + er4.x + e4.x));
        m.y = fmaxf(m.y, lrelu(l4.y + er4.y + e4.y));
        m.z = fmaxf(m.z, lrelu(l4.z + er4.z + e4.z));
        m.w = fmaxf(m.w, lrelu(l4.w + er4.w + e4.w));
    }
#pragma unroll
    for (int d = 16; d; d >>= 1) {
        m.x = fmaxf(m.x, __shfl_xor_sync(0xffffffffu, m.x, d));
        m.y = fmaxf(m.y, __shfl_xor_sync(0xffffffffu, m.y, d));
        m.z = fmaxf(m.z, __shfl_xor_sync(0xffffffffu, m.z, d));
        m.w = fmaxf(m.w, __shfl_xor_sync(0xffffffffu, m.w, d));
    }

    float4 ss = make_float4(0.f, 0.f, 0.f, 0.f);
#pragma unroll
    for (int c = 0; c < 4; c++) {
        int k = lane + 32 * c;
        if (k < deg) {
            float4 ex;
            ex.x = __expf(vc[c].x - m.x);
            ex.y = __expf(vc[c].y - m.y);
            ex.z = __expf(vc[c].z - m.z);
            ex.w = __expf(vc[c].w - m.w);
            vc[c] = ex;
            ss.x += ex.x; ss.y += ex.y; ss.z += ex.z; ss.w += ex.w;
        }
    }
    for (int k = lane + 128; k < deg; k += 32) {
        int e = g_eidx[s0 + k];
        int s = src[e];
        int et = efeat[e];
        float4 l4 = *(const float4*)(g_el + s * 4);
        float4 e4 = *(const float4*)(g_ee + et * 4);
        ss.x += __expf(lrelu(l4.x + er4.x + e4.x) - m.x);
        ss.y += __expf(lrelu(l4.y + er4.y + e4.y) - m.y);
        ss.z += __expf(lrelu(l4.z + er4.z + e4.z) - m.z);
        ss.w += __expf(lrelu(l4.w + er4.w + e4.w) - m.w);
    }
#pragma unroll
    for (int d = 16; d; d >>= 1) {
        ss.x += __shfl_xor_sync(0xffffffffu, ss.x, d);
        ss.y += __shfl_xor_sync(0xffffffffu, ss.y, d);
        ss.z += __shfl_xor_sync(0xffffffffu, ss.z, d);
        ss.w += __shfl_xor_sync(0xffffffffu, ss.w, d);
    }
    float4 invd = make_float4(1.f / ss.x, 1.f / ss.y, 1.f / ss.z, 1.f / ss.w);

    int h0 = (lane * 4) / 96;
    int h1 = (128 + lane * 4) / 96;
    int h2 = (256 + lane * 4) / 96;
    float id0 = pick4(invd, h0), id1 = pick4(invd, h1), id2 = pick4(invd, h2);

    float4 a0 = make_float4(0.f, 0.f, 0.f, 0.f), a1 = a0, a2 = a0;
#pragma unroll
    for (int c = 0; c < 4; c++) {
        int cnt = deg - c * 32;
        if (cnt <= 0) break;
        if (cnt > 32) cnt = 32;
        for (int l = 0; l < cnt; l++) {
            int s = __shfl_sync(0xffffffffu, sc[c], l);
            float ex_x = __shfl_sync(0xffffffffu, vc[c].x, l);
            float ex_y = __shfl_sync(0xffffffffu, vc[c].y, l);
            float ex_z = __shfl_sync(0xffffffffu, vc[c].z, l);
            float ex_w = __shfl_sync(0xffffffffu, vc[c].w, l);
            float4 exv = make_float4(ex_x, ex_y, ex_z, ex_w);
            float w0 = pick4(exv, h0) * id0;
            float w1 = pick4(exv, h1) * id1;
            float w2 = pick4(exv, h2) * id2;
            const float4* f4 = (const float4*)(g_ft + (size_t)s * FDIM);
            float4 p0 = f4[lane];
            float4 p1 = f4[32 + lane];
            float4 p2 = f4[64 + lane];
            a0.x += p0.x * w0; a0.y += p0.y * w0; a0.z += p0.z * w0; a0.w += p0.w * w0;
            a1.x += p1.x * w1; a1.y += p1.y * w1; a1.z += p1.z * w1; a1.w += p1.w * w1;
            a2.x += p2.x * w2; a2.y += p2.y * w2; a2.z += p2.z * w2; a2.w += p2.w * w2;
        }
    }
    // tail (deg > 128): all lanes recompute per edge (broadcast loads)
    for (int k = 128; k < deg; k++) {
        int e = g_eidx[s0 + k];
        int s = src[e];
        int et = efeat[e];
        float4 l4 = *(const float4*)(g_el + s * 4);
        float4 e4 = *(const float4*)(g_ee + et * 4);
        float4 exv;
        exv.x = __expf(lrelu(l4.x + er4.x + e4.x) - m.x);
        exv.y = __expf(lrelu(l4.y + er4.y + e4.y) - m.y);
        exv.z = __expf(lrelu(l4.z + er4.z + e4.z) - m.z);
        exv.w = __expf(lrelu(l4.w + er4.w + e4.w) - m.w);
        float w0 = pick4(exv, h0) * id0;
        float w1 = pick4(exv, h1) * id1;
        float w2 = pick4(exv, h2) * id2;
        const float4* f4 = (const float4*)(g_ft + (size_t)s * FDIM);
        float4 p0 = f4[lane];
        float4 p1 = f4[32 + lane];
        float4 p2 = f4[64 + lane];
        a0.x += p0.x * w0; a0.y += p0.y * w0; a0.z += p0.z * w0; a0.w += p0.w * w0;
        a1.x += p1.x * w1; a1.y += p1.y * w1; a1.z += p1.z * w1; a1.w += p1.w * w1;
        a2.x += p2.x * w2; a2.y += p2.y * w2; a2.z += p2.z * w2; a2.w += p2.w * w2;
    }

    float4* o4 = (float4*)(out + (size_t)n * FDIM);
    float4 q;
    q = o4[lane];      q.x += a0.x; q.y += a0.y; q.z += a0.z; q.w += a0.w; o4[lane] = q;
    q = o4[32 + lane]; q.x += a1.x; q.y += a1.y; q.z += a1.z; q.w += a1.w; o4[32 + lane] = q;
    q = o4[64 + lane]; q.x += a2.x; q.y += a2.y; q.z += a2.z; q.w += a2.w; o4[64 + lane] = q;
}

// ---------------------------------------------------------------------------
extern "C" void kernel_launch(void* const* d_in, const int* in_sizes, int n_in,
                              void* d_out, int out_size) {
    const float* feat   = (const float*)d_in[0];
    const int*   e_feat = (const int*)d_in[1];
    const int*   src    = (const int*)d_in[2];
    const int*   dst    = (const int*)d_in[3];
    const float* fc     = (const float*)d_in[4];
    const float* resw   = (const float*)d_in[5];
    const float* emb    = (const float*)d_in[6];
    const float* fce    = (const float*)d_in[7];
    const float* attn_l = (const float*)d_in[8];
    const float* attn_r = (const float*)d_in[9];
    const float* attn_e = (const float*)d_in[10];
    float* out = (float*)d_out;

    int N = in_sizes[0] / FEAT_IN;
    int E = in_sizes[1];

    cudaFuncSetAttribute(k1_transform, cudaFuncAttributeMaxDynamicSharedMemorySize,
                         K1_SMEM_FLOATS * (int)sizeof(float));

    // CSR build
    k_zero<<<(N + 256) / 256, 256>>>(N);
    k_count<<<(E + 255) / 256, 256>>>(dst, E);
    k_scan<<<1, 1024>>>(N);
    k_scatter<<<(E + 255) / 256, 256>>>(dst, E);

    // tiny ee table
    k_ee<<<1, 640>>>(emb, fce, attn_e);

    // node transform: ft + residual (residual written to out)
    k1_transform<<<148, 256, K1_SMEM_FLOATS * (int)sizeof(float)>>>(feat, fc, resw, out, N);

    // per-node attention logits
    k2_elr<<<(N + 7) / 8, 256>>>(attn_l, attn_r, N);

    // edge softmax + aggregation
    k7_agg<<<(N + 7) / 8, 256>>>(src, e_feat, out, N);
}

// round 2
// speedup vs baseline: 1.1768x; 1.1768x over previous
#include <cuda_runtime.h>

#define T_ 3
#define H_ 4
#define DIN 64
#define FEAT_IN 192     /* T_*DIN */
#define FDIM 384        /* H_ * T_*32 */
#define EF_ 64
#define NET 5
#define MAXN 50000
#define MAXE 400000
#define NEG_SLOPE 0.2f

typedef unsigned long long ull;

__device__ float g_ft[(size_t)MAXN * FDIM];
__device__ float g_el[MAXN * H_];
__device__ float g_er[MAXN * H_];
__device__ float g_ee[32];
__device__ int   g_cnt[MAXN + 1];
__device__ int   g_off[MAXN + 1];
__device__ int   g_cur[MAXN + 1];
__device__ int   g_eidx[MAXE];
__device__ int   g_part[256];

__device__ __forceinline__ ull pack2(float x, float y) {
    ull r; asm("mov.b64 %0, {%1,%2};" : "=l"(r) : "f"(x), "f"(y)); return r;
}
__device__ __forceinline__ ull fma2(ull a, ull b, ull c) {
    ull d; asm("fma.rn.f32x2 %0, %1, %2, %3;" : "=l"(d) : "l"(a), "l"(b), "l"(c)); return d;
}
__device__ __forceinline__ void stcs64(float* p, ull v) {
    asm volatile("st.global.cs.u64 [%0], %1;" :: "l"(p), "l"(v) : "memory");
}
__device__ __forceinline__ float lrelu(float x) { return x >= 0.f ? x : NEG_SLOPE * x; }
__device__ __forceinline__ float pick4(float4 v, int h) {
    float r = v.x;
    r = (h == 1) ? v.y : r;
    r = (h == 2) ? v.z : r;
    r = (h == 3) ? v.w : r;
    return r;
}

// ---------------------------------------------------------------------------
// CSR build
// ---------------------------------------------------------------------------
__global__ void k_zero(int N) {
    int i = blockIdx.x * blockDim.x + threadIdx.x;
    if (i <= N) g_cnt[i] = 0;
}

__global__ void k_count(const int* __restrict__ dst, int E) {
    int i = blockIdx.x * blockDim.x + threadIdx.x;
    int base = i * 4;
    if (base + 3 < E) {
        int4 d = *(const int4*)(dst + base);
        atomicAdd(&g_cnt[d.x], 1);
        atomicAdd(&g_cnt[d.y], 1);
        atomicAdd(&g_cnt[d.z], 1);
        atomicAdd(&g_cnt[d.w], 1);
    } else {
        for (int e = base; e < E; e++) atomicAdd(&g_cnt[dst[e]], 1);
    }
}

// hierarchical scan over N+1 entries: block partials -> scan partials -> apply
__global__ void k_scan1(int N) {
    __shared__ int wsum[16];
    int t = threadIdx.x;
    int idx = blockIdx.x * 512 + t;
    int lane = t & 31, w = t >> 5;
    int x = (idx <= N) ? g_cnt[idx] : 0;
    int incl = x;
#pragma unroll
    for (int d = 1; d < 32; d <<= 1) {
        int y = __shfl_up_sync(0xffffffffu, incl, d);
        if (lane >= d) incl += y;
    }
    if (lane == 31) wsum[w] = incl;
    __syncthreads();
    if (t < 32) {
        int s = (t < 16) ? wsum[t] : 0;
#pragma unroll
        for (int d = 1; d < 16; d <<= 1) {
            int y = __shfl_up_sync(0xffffffffu, s, d);
            if (t >= d) s += y;
        }
        if (t < 16) wsum[t] = s;
    }
    __syncthreads();
    int excl = (w ? wsum[w - 1] : 0) + incl - x;
    if (idx <= N) g_off[idx] = excl;
    if (t == 0) g_part[blockIdx.x] = wsum[15];
}

__global__ void k_scan2(int P) {
    __shared__ int sm[256];
    int t = threadIdx.x;
    int v = (t < P) ? g_part[t] : 0;
    sm[t] = v;
    __syncthreads();
    for (int d = 1; d < 256; d <<= 1) {
        int y = (t >= d) ? sm[t - d] : 0;
        __syncthreads();
        sm[t] += y;
        __syncthreads();
    }
    if (t < P) g_part[t] = sm[t] - v;  // exclusive
}

__global__ void k_scan3(int N) {
    int idx = blockIdx.x * 512 + threadIdx.x;
    if (idx <= N) {
        int o = g_off[idx] + g_part[blockIdx.x];
        g_off[idx] = o;
        g_cur[idx] = o;
    }
}

__global__ void k_scatter(const int* __restrict__ dst, int E) {
    int i = blockIdx.x * blockDim.x + threadIdx.x;
    int base = i * 4;
    if (base + 3 < E) {
        int4 d = *(const int4*)(dst + base);
        int p0 = atomicAdd(&g_cur[d.x], 1);
        int p1 = atomicAdd(&g_cur[d.y], 1);
        int p2 = atomicAdd(&g_cur[d.z], 1);
        int p3 = atomicAdd(&g_cur[d.w], 1);
        g_eidx[p0] = base;
        g_eidx[p1] = base + 1;
        g_eidx[p2] = base + 2;
        g_eidx[p3] = base + 3;
    } else {
        for (int e = base; e < E; e++) {
            int p = atomicAdd(&g_cur[dst[e]], 1);
            g_eidx[p] = e;
        }
    }
}

// ---------------------------------------------------------------------------
// ee table: ee[et][h] = sum_f attn_e[h,f] * (edge_emb[et] . fc_e_w[h*64+f, :])
// ---------------------------------------------------------------------------
__global__ void k_ee(const float* __restrict__ emb, const float* __restrict__ fce,
                     const float* __restrict__ attn_e) {
    int w = threadIdx.x >> 5;
    int lane = threadIdx.x & 31;
    if (w >= NET * H_) return;
    int et = w / H_, h = w % H_;
    float acc = 0.f;
    for (int f = lane; f < EF_; f += 32) {
        const float* row = fce + (h * EF_ + f) * EF_;
        float inner = 0.f;
#pragma unroll 8
        for (int k = 0; k < EF_; k++) inner += emb[et * EF_ + k] * row[k];
        acc += inner * attn_e[h * EF_ + f];
    }
#pragma unroll
    for (int d = 16; d; d >>= 1) acc += __shfl_xor_sync(0xffffffffu, acc, d);
    if (lane == 0) g_ee[et * H_ + h] = acc;
}

// ---------------------------------------------------------------------------
// k1: node transform + fused el/er.
// ft -> g_ft, residual -> out (streaming store), el/er -> g_el/g_er.
// ---------------------------------------------------------------------------
#define K1_SMEM_FLOATS (2 * T_ * DIN * 128 + 32 * FEAT_IN)  /* 55296 */
__global__ void __launch_bounds__(256) k1_transform(
    const float* __restrict__ feat, const float* __restrict__ fc,
    const float* __restrict__ resw, const float* __restrict__ attn_l,
    const float* __restrict__ attn_r, float* __restrict__ out, int N) {
    extern __shared__ float sh[];
    float* wf = sh;
    float* wr = sh + T_ * DIN * 128;
    float* sf = sh + 2 * T_ * DIN * 128;
    for (int i = threadIdx.x; i < T_ * DIN * 128; i += blockDim.x) {
        wf[i] = fc[i];
        wr[i] = resw[i];
    }
    int c2 = threadIdx.x & 63;
    int grp = threadIdx.x >> 6;
    int lane = threadIdx.x & 31;
    int j0 = c2 * 2;
    int hb = (j0 >> 5) * 96 + (j0 & 31);  // h*96 + o
    int myh = 2 * ((threadIdx.x >> 5) & 1) + (lane >> 4);

    // preload attention vector entries for this thread's 2 columns x 3 slots
    float alv[T_][2], arv[T_][2];
#pragma unroll
    for (int t = 0; t < T_; t++) {
        alv[t][0] = attn_l[hb + t * 32];
        alv[t][1] = attn_l[hb + t * 32 + 1];
        arv[t][0] = attn_r[hb + t * 32];
        arv[t][1] = attn_r[hb + t * 32 + 1];
    }
    __syncthreads();

    for (int n0 = blockIdx.x * 32; n0 < N; n0 += gridDim.x * 32) {
        __syncthreads();
        int cnt = min(32, N - n0) * FEAT_IN;
        for (int i = threadIdx.x; i < cnt; i += blockDim.x)
            sf[i] = __ldcs(feat + (size_t)n0 * FEAT_IN + i);
        __syncthreads();

        float elp[8], erp[8];
#pragma unroll
        for (int i = 0; i < 8; i++) { elp[i] = 0.f; erp[i] = 0.f; }

#pragma unroll
        for (int t = 0; t < T_; t++) {
            ull af[8], ar_[8];
#pragma unroll
            for (int i = 0; i < 8; i++) { af[i] = 0ull; ar_[i] = 0ull; }
            const float* wfp = wf + t * DIN * 128 + j0;
            const float* wrp = wr + t * DIN * 128 + j0;
            const float* fp = sf + (grp * 8) * FEAT_IN + t * DIN;
#pragma unroll 4
            for (int d = 0; d < DIN; d++) {
                ull w2f = *(const ull*)(wfp + d * 128);
                ull w2r = *(const ull*)(wrp + d * 128);
#pragma unroll
                for (int i = 0; i < 8; i++) {
                    float fv = fp[i * FEAT_IN + d];
                    ull f2 = pack2(fv, fv);
                    af[i] = fma2(f2, w2f, af[i]);
                    ar_[i] = fma2(f2, w2r, ar_[i]);
                }
            }
#pragma unroll
            for (int i = 0; i < 8; i++) {
                float lo = __uint_as_float((unsigned)(af[i] & 0xffffffffull));
                float hi = __uint_as_float((unsigned)(af[i] >> 32));
                elp[i] += lo * alv[t][0] + hi * alv[t][1];
                erp[i] += lo * arv[t][0] + hi * arv[t][1];
                int n = n0 + grp * 8 + i;
                if (n < N) {
                    size_t idx = (size_t)n * FDIM + hb + t * 32;
                    *(ull*)(g_ft + idx) = af[i];
                    stcs64(out + idx, ar_[i]);
                }
            }
        }
        // reduce elp/erp over the 16 lanes sharing this head
#pragma unroll
        for (int i = 0; i < 8; i++) {
#pragma unroll
            for (int d = 8; d; d >>= 1) {
                elp[i] += __shfl_xor_sync(0xffffffffu, elp[i], d);
                erp[i] += __shfl_xor_sync(0xffffffffu, erp[i], d);
            }
        }
        if ((lane & 15) == 0) {
#pragma unroll
            for (int i = 0; i < 8; i++) {
                int n = n0 + grp * 8 + i;
                if (n < N) {
                    g_el[n * 4 + myh] = elp[i];
                    g_er[n * 4 + myh] = erp[i];
                }
            }
        }
    }
}

// ---------------------------------------------------------------------------
// k7: softmax + aggregation. One warp per dst node; smem-staged (src, weight)
// then gather loop unrolled x4 for MLP.
// ---------------------------------------------------------------------------
__global__ void __launch_bounds__(256) k7_agg(const int* __restrict__ src,
                                              const int* __restrict__ efeat,
                                              float* __restrict__ out, int N) {
    __shared__ int ssm[8][128];
    __shared__ float4 wsm[8][128];
    int wl = threadIdx.x >> 5;
    int n = (blockIdx.x * blockDim.x + threadIdx.x) >> 5;
    int lane = threadIdx.x & 31;
    if (n >= N) return;
    int s0 = g_off[n];
    int deg = g_off[n + 1] - s0;
    if (deg == 0) return;

    float4 er4 = *(const float4*)(g_er + n * 4);

    float4 vc[4];
    int sc[4];
    float4 m = make_float4(-1e30f, -1e30f, -1e30f, -1e30f);
#pragma unroll
    for (int c = 0; c < 4; c++) {
        int k = lane + 32 * c;
        sc[c] = 0;
        vc[c] = make_float4(0.f, 0.f, 0.f, 0.f);
        if (k < deg) {
            int e = g_eidx[s0 + k];
            int s = src[e];
            int et = efeat[e];
            float4 l4 = *(const float4*)(g_el + s * 4);
            float4 e4 = *(const float4*)(g_ee + et * 4);
            float4 v;
            v.x = lrelu(l4.x + er4.x + e4.x);
            v.y = lrelu(l4.y + er4.y + e4.y);
            v.z = lrelu(l4.z + er4.z + e4.z);
            v.w = lrelu(l4.w + er4.w + e4.w);
            sc[c] = s;
            vc[c] = v;
            m.x = fmaxf(m.x, v.x); m.y = fmaxf(m.y, v.y);
            m.z = fmaxf(m.z, v.z); m.w = fmaxf(m.w, v.w);
        }
    }
    for (int k = lane + 128; k < deg; k += 32) {
        int e = g_eidx[s0 + k];
        int s = src[e];
        int et = efeat[e];
        float4 l4 = *(const float4*)(g_el + s * 4);
        float4 e4 = *(const float4*)(g_ee + et * 4);
        m.x = fmaxf(m.x, lrelu(l4.x + er4.x + e4.x));
        m.y = fmaxf(m.y, lrelu(l4.y + er4.y + e4.y));
        m.z = fmaxf(m.z, lrelu(l4.z + er4.z + e4.z));
        m.w = fmaxf(m.w, lrelu(l4.w + er4.w + e4.w));
    }
#pragma unroll
    for (int d = 16; d; d >>= 1) {
        m.x = fmaxf(m.x, __shfl_xor_sync(0xffffffffu, m.x, d));
        m.y = fmaxf(m.y, __shfl_xor_sync(0xffffffffu, m.y, d));
        m.z = fmaxf(m.z, __shfl_xor_sync(0xffffffffu, m.z, d));
        m.w = fmaxf(m.w, __shfl_xor_sync(0xffffffffu, m.w, d));
    }

    float4 ss = make_float4(0.f, 0.f, 0.f, 0.f);
#pragma unroll
    for (int c = 0; c < 4; c++) {
        int k = lane + 32 * c;
        if (k < deg) {
            float4 ex;
            ex.x = __expf(vc[c].x - m.x);
            ex.y = __expf(vc[c].y - m.y);
            ex.z = __expf(vc[c].z - m.z);
            ex.w = __expf(vc[c].w - m.w);
            vc[c] = ex;
            ss.x += ex.x; ss.y += ex.y; ss.z += ex.z; ss.w += ex.w;
        }
    }
    for (int k = lane + 128; k < deg; k += 32) {
        int e = g_eidx[s0 + k];
        int s = src[e];
        int et = efeat[e];
        float4 l4 = *(const float4*)(g_el + s * 4);
        float4 e4 = *(const float4*)(g_ee + et * 4);
        ss.x += __expf(lrelu(l4.x + er4.x + e4.x) - m.x);
        ss.y += __expf(lrelu(l4.y + er4.y + e4.y) - m.y);
        ss.z += __expf(lrelu(l4.z + er4.z + e4.z) - m.z);
        ss.w += __expf(lrelu(l4.w + er4.w + e4.w) - m.w);
    }
#pragma unroll
    for (int d = 16; d; d >>= 1) {
        ss.x += __shfl_xor_sync(0xffffffffu, ss.x, d);
        ss.y += __shfl_xor_sync(0xffffffffu, ss.y, d);
        ss.z += __shfl_xor_sync(0xffffffffu, ss.z, d);
        ss.w += __shfl_xor_sync(0xffffffffu, ss.w, d);
    }
    float4 invd = make_float4(1.f / ss.x, 1.f / ss.y, 1.f / ss.z, 1.f / ss.w);

    // stage (src, normalized weight per head) into smem
#pragma unroll
    for (int c = 0; c < 4; c++) {
        int k = lane + 32 * c;
        if (k < deg && k < 128) {
            ssm[wl][k] = sc[c];
            wsm[wl][k] = make_float4(vc[c].x * invd.x, vc[c].y * invd.y,
                                     vc[c].z * invd.z, vc[c].w * invd.w);
        }
    }
    __syncwarp();

    int h0 = (lane * 4) / 96;
    int h1 = (128 + lane * 4) / 96;
    int h2 = (256 + lane * 4) / 96;

    float4 a0 = make_float4(0.f, 0.f, 0.f, 0.f), a1 = a0, a2 = a0;
    int total = min(deg, 128);
    int k = 0;
    for (; k + 4 <= total; k += 4) {
        int s_[4];
        float4 w_[4];
#pragma unroll
        for (int u = 0; u < 4; u++) { s_[u] = ssm[wl][k + u]; w_[u] = wsm[wl][k + u]; }
        float4 p[4][3];
#pragma unroll
        for (int u = 0; u < 4; u++) {
            const float4* f4 = (const float4*)(g_ft + (size_t)s_[u] * FDIM);
            p[u][0] = f4[lane];
            p[u][1] = f4[32 + lane];
            p[u][2] = f4[64 + lane];
        }
#pragma unroll
        for (int u = 0; u < 4; u++) {
            float w0 = pick4(w_[u], h0), w1 = pick4(w_[u], h1), w2 = pick4(w_[u], h2);
            a0.x += p[u][0].x * w0; a0.y += p[u][0].y * w0; a0.z += p[u][0].z * w0; a0.w += p[u][0].w * w0;
            a1.x += p[u][1].x * w1; a1.y += p[u][1].y * w1; a1.z += p[u][1].z * w1; a1.w += p[u][1].w * w1;
            a2.x += p[u][2].x * w2; a2.y += p[u][2].y * w2; a2.z += p[u][2].z * w2; a2.w += p[u][2].w * w2;
        }
    }
    for (; k < total; k++) {
        int s = ssm[wl][k];
        float4 w4 = wsm[wl][k];
        float w0 = pick4(w4, h0), w1 = pick4(w4, h1), w2 = pick4(w4, h2);
        const float4* f4 = (const float4*)(g_ft + (size_t)s * FDIM);
        float4 p0 = f4[lane], p1 = f4[32 + lane], p2 = f4[64 + lane];
        a0.x += p0.x * w0; a0.y += p0.y * w0; a0.z += p0.z * w0; a0.w += p0.w * w0;
        a1.x += p1.x * w1; a1.y += p1.y * w1; a1.z += p1.z * w1; a1.w += p1.w * w1;
        a2.x += p2.x * w2; a2.y += p2.y * w2; a2.z += p2.z * w2; a2.w += p2.w * w2;
    }
    // tail (deg > 128): recompute weights per edge, broadcast loads
    for (int kk = 128; kk < deg; kk++) {
        int e = g_eidx[s0 + kk];
        int s = src[e];
        int et = efeat[e];
        float4 l4 = *(const float4*)(g_el + s * 4);
        float4 e4 = *(const float4*)(g_ee + et * 4);
        float4 exv;
        exv.x = __expf(lrelu(l4.x + er4.x + e4.x) - m.x) * invd.x;
        exv.y = __expf(lrelu(l4.y + er4.y + e4.y) - m.y) * invd.y;
        exv.z = __expf(lrelu(l4.z + er4.z + e4.z) - m.z) * invd.z;
        exv.w = __expf(lrelu(l4.w + er4.w + e4.w) - m.w) * invd.w;
        float w0 = pick4(exv, h0), w1 = pick4(exv, h1), w2 = pick4(exv, h2);
        const float4* f4 = (const float4*)(g_ft + (size_t)s * FDIM);
        float4 p0 = f4[lane], p1 = f4[32 + lane], p2 = f4[64 + lane];
        a0.x += p0.x * w0; a0.y += p0.y * w0; a0.z += p0.z * w0; a0.w += p0.w * w0;
        a1.x += p1.x * w1; a1.y += p1.y * w1; a1.z += p1.z * w1; a1.w += p1.w * w1;
        a2.x += p2.x * w2; a2.y += p2.y * w2; a2.z += p2.z * w2; a2.w += p2.w * w2;
    }

    float4* o4 = (float4*)(out + (size_t)n * FDIM);
    float4 q;
    q = o4[lane];      q.x += a0.x; q.y += a0.y; q.z += a0.z; q.w += a0.w; o4[lane] = q;
    q = o4[32 + lane]; q.x += a1.x; q.y += a1.y; q.z += a1.z; q.w += a1.w; o4[32 + lane] = q;
    q = o4[64 + lane]; q.x += a2.x; q.y += a2.y; q.z += a2.z; q.w += a2.w; o4[64 + lane] = q;
}

// ---------------------------------------------------------------------------
extern "C" void kernel_launch(void* const* d_in, const int* in_sizes, int n_in,
                              void* d_out, int out_size) {
    const float* feat   = (const float*)d_in[0];
    const int*   e_feat = (const int*)d_in[1];
    const int*   src    = (const int*)d_in[2];
    const int*   dst    = (const int*)d_in[3];
    const float* fc     = (const float*)d_in[4];
    const float* resw   = (const float*)d_in[5];
    const float* emb    = (const float*)d_in[6];
    const float* fce    = (const float*)d_in[7];
    const float* attn_l = (const float*)d_in[8];
    const float* attn_r = (const float*)d_in[9];
    const float* attn_e = (const float*)d_in[10];
    float* out = (float*)d_out;

    int N = in_sizes[0] / FEAT_IN;
    int E = in_sizes[1];

    cudaFuncSetAttribute(k1_transform, cudaFuncAttributeMaxDynamicSharedMemorySize,
                         K1_SMEM_FLOATS * (int)sizeof(float));

    int scanBlocks = (N + 1 + 511) / 512;

    // CSR build
    k_zero<<<(N + 256) / 256, 256>>>(N);
    k_count<<<(E / 4 + 255) / 256, 256>>>(dst, E);
    k_scan1<<<scanBlocks, 512>>>(N);
    k_scan2<<<1, 256>>>(scanBlocks);
    k_scan3<<<scanBlocks, 512>>>(N);
    k_scatter<<<(E / 4 + 255) / 256, 256>>>(dst, E);

    // tiny ee table
    k_ee<<<1, 640>>>(emb, fce, attn_e);

    // node transform: ft + residual + el/er (fused)
    k1_transform<<<148, 256, K1_SMEM_FLOATS * (int)sizeof(float)>>>(
        feat, fc, resw, attn_l, attn_r, out, N);

    // edge softmax + aggregation
    k7_agg<<<(N + 7) / 8, 256>>>(src, e_feat, out, N);
}

// round 3
// speedup vs baseline: 1.4400x; 1.2237x over previous
#include <cuda_runtime.h>

#define T_ 3
#define H_ 4
#define DIN 64
#define FEAT_IN 192     /* T_*DIN */
#define FDIM 384        /* H_ * T_*32 */
#define EF_ 64
#define NET 5
#define MAXN 50000
#define MAXE 400000
#define NEG_SLOPE 0.2f
#define PADN 36

typedef unsigned long long ull;

__device__ float g_ft[(size_t)MAXN * FDIM];
__device__ float g_el[MAXN * H_];
__device__ float g_er[MAXN * H_];
__device__ float g_ee[32];
__device__ int   g_cnt[MAXN + 1];
__device__ int   g_off[MAXN + 1];
__device__ int   g_cur[MAXN + 1];
__device__ int   g_eidx[MAXE];
__device__ int   g_part[256];

__device__ __forceinline__ ull pack2(float x, float y) {
    ull r; asm("mov.b64 %0, {%1,%2};" : "=l"(r) : "f"(x), "f"(y)); return r;
}
__device__ __forceinline__ ull fma2(ull a, ull b, ull c) {
    ull d; asm("fma.rn.f32x2 %0, %1, %2, %3;" : "=l"(d) : "l"(a), "l"(b), "l"(c)); return d;
}
__device__ __forceinline__ float lo2(ull v) { return __uint_as_float((unsigned)(v & 0xffffffffull)); }
__device__ __forceinline__ float hi2(ull v) { return __uint_as_float((unsigned)(v >> 32)); }
__device__ __forceinline__ void stcs32(float* p, float v) {
    asm volatile("st.global.cs.f32 [%0], %1;" :: "l"(p), "f"(v) : "memory");
}
__device__ __forceinline__ float lrelu(float x) { return x >= 0.f ? x : NEG_SLOPE * x; }
__device__ __forceinline__ float pick4(float4 v, int h) {
    float r = v.x;
    r = (h == 1) ? v.y : r;
    r = (h == 2) ? v.z : r;
    r = (h == 3) ? v.w : r;
    return r;
}

// ---------------------------------------------------------------------------
// CSR build
// ---------------------------------------------------------------------------
__global__ void k_zero(int N) {
    int i = blockIdx.x * blockDim.x + threadIdx.x;
    if (i <= N) g_cnt[i] = 0;
}

__global__ void k_count(const int* __restrict__ dst, int E) {
    int i = blockIdx.x * blockDim.x + threadIdx.x;
    int base = i * 4;
    if (base + 3 < E) {
        int4 d = *(const int4*)(dst + base);
        atomicAdd(&g_cnt[d.x], 1);
        atomicAdd(&g_cnt[d.y], 1);
        atomicAdd(&g_cnt[d.z], 1);
        atomicAdd(&g_cnt[d.w], 1);
    } else {
        for (int e = base; e < E; e++) atomicAdd(&g_cnt[dst[e]], 1);
    }
}

__global__ void k_scan1(int N) {
    __shared__ int wsum[16];
    int t = threadIdx.x;
    int idx = blockIdx.x * 512 + t;
    int lane = t & 31, w = t >> 5;
    int x = (idx <= N) ? g_cnt[idx] : 0;
    int incl = x;
#pragma unroll
    for (int d = 1; d < 32; d <<= 1) {
        int y = __shfl_up_sync(0xffffffffu, incl, d);
        if (lane >= d) incl += y;
    }
    if (lane == 31) wsum[w] = incl;
    __syncthreads();
    if (t < 32) {
        int s = (t < 16) ? wsum[t] : 0;
#pragma unroll
        for (int d = 1; d < 16; d <<= 1) {
            int y = __shfl_up_sync(0xffffffffu, s, d);
            if (t >= d) s += y;
        }
        if (t < 16) wsum[t] = s;
    }
    __syncthreads();
    int excl = (w ? wsum[w - 1] : 0) + incl - x;
    if (idx <= N) g_off[idx] = excl;
    if (t == 0) g_part[blockIdx.x] = wsum[15];
}

__global__ void k_scan2(int P) {
    __shared__ int sm[256];
    int t = threadIdx.x;
    int v = (t < P) ? g_part[t] : 0;
    sm[t] = v;
    __syncthreads();
    for (int d = 1; d < 256; d <<= 1) {
        int y = (t >= d) ? sm[t - d] : 0;
        __syncthreads();
        sm[t] += y;
        __syncthreads();
    }
    if (t < P) g_part[t] = sm[t] - v;  // exclusive
}

__global__ void k_scan3(int N) {
    int idx = blockIdx.x * 512 + threadIdx.x;
    if (idx <= N) {
        int o = g_off[idx] + g_part[blockIdx.x];
        g_off[idx] = o;
        g_cur[idx] = o;
    }
}

__global__ void k_scatter(const int* __restrict__ dst, int E) {
    int i = blockIdx.x * blockDim.x + threadIdx.x;
    int base = i * 4;
    if (base + 3 < E) {
        int4 d = *(const int4*)(dst + base);
        int p0 = atomicAdd(&g_cur[d.x], 1);
        int p1 = atomicAdd(&g_cur[d.y], 1);
        int p2 = atomicAdd(&g_cur[d.z], 1);
        int p3 = atomicAdd(&g_cur[d.w], 1);
        g_eidx[p0] = base;
        g_eidx[p1] = base + 1;
        g_eidx[p2] = base + 2;
        g_eidx[p3] = base + 3;
    } else {
        for (int e = base; e < E; e++) {
            int p = atomicAdd(&g_cur[dst[e]], 1);
            g_eidx[p] = e;
        }
    }
}

// ---------------------------------------------------------------------------
// ee table
// ---------------------------------------------------------------------------
__global__ void k_ee(const float* __restrict__ emb, const float* __restrict__ fce,
                     const float* __restrict__ attn_e) {
    int w = threadIdx.x >> 5;
    int lane = threadIdx.x & 31;
    if (w >= NET * H_) return;
    int et = w / H_, h = w % H_;
    float acc = 0.f;
    for (int f = lane; f < EF_; f += 32) {
        const float* row = fce + (h * EF_ + f) * EF_;
        float inner = 0.f;
#pragma unroll 8
        for (int k = 0; k < EF_; k++) inner += emb[et * EF_ + k] * row[k];
        acc += inner * attn_e[h * EF_ + f];
    }
#pragma unroll
    for (int d = 16; d; d >>= 1) acc += __shfl_xor_sync(0xffffffffu, acc, d);
    if (lane == 0) g_ee[et * H_ + h] = acc;
}

// ---------------------------------------------------------------------------
// k1: node transform + fused el/er. f32x2 packs NODE PAIRS; feat tile stored
// transposed in SMEM so feature pairs are single LDS.64 broadcasts.
// Thread owns one output column j (0..127) and 16 nodes (8 pairs).
// ---------------------------------------------------------------------------
#define K1_SMEM_FLOATS (2 * T_ * DIN * 128 + T_ * DIN * PADN)  /* 56064 = 224256 B */
__global__ void __launch_bounds__(256) k1_transform(
    const float* __restrict__ feat, const float* __restrict__ fc,
    const float* __restrict__ resw, const float* __restrict__ attn_l,
    const float* __restrict__ attn_r, float* __restrict__ out, int N) {
    extern __shared__ float sh[];
    float* wf = sh;                          // [t*64+d][128]
    float* wr = sh + T_ * DIN * 128;
    float* sft = sh + 2 * T_ * DIN * 128;    // [t*64+d][PADN]
    for (int i = threadIdx.x; i < T_ * DIN * 128; i += blockDim.x) {
        wf[i] = fc[i];
        wr[i] = resw[i];
    }
    int j = threadIdx.x & 127;               // output column within 128
    int half = threadIdx.x >> 7;             // node half: 0 -> nodes 0..15, 1 -> 16..31
    int h = j >> 5;
    int hb = h * 96 + (j & 31);
    int lane = threadIdx.x & 31;

    ull al2[T_], ar2[T_];
#pragma unroll
    for (int t = 0; t < T_; t++) {
        float a = attn_l[hb + t * 32];
        float b = attn_r[hb + t * 32];
        al2[t] = pack2(a, a);
        ar2[t] = pack2(b, b);
    }
    __syncthreads();

    for (int n0 = blockIdx.x * 32; n0 < N; n0 += gridDim.x * 32) {
        __syncthreads();
        int nNodes = min(32, N - n0);
        // transposed tile load: sft[k][n] = feat[n0+n][k]
        for (int i = threadIdx.x; i < 32 * 48; i += 256) {
            int n = i / 48, q = i % 48;
            float4 v = (n < nNodes)
                ? __ldcs((const float4*)(feat + (size_t)(n0 + n) * FEAT_IN) + q)
                : make_float4(0.f, 0.f, 0.f, 0.f);
            int k = q * 4;
            sft[(k + 0) * PADN + n] = v.x;
            sft[(k + 1) * PADN + n] = v.y;
            sft[(k + 2) * PADN + n] = v.z;
            sft[(k + 3) * PADN + n] = v.w;
        }
        __syncthreads();

        ull elp[8], erp[8];
#pragma unroll
        for (int p = 0; p < 8; p++) { elp[p] = 0ull; erp[p] = 0ull; }

#pragma unroll
        for (int t = 0; t < T_; t++) {
            ull af[8], ar[8];
#pragma unroll
            for (int p = 0; p < 8; p++) { af[p] = 0ull; ar[p] = 0ull; }
            const float* wfp = wf + (t * DIN) * 128 + j;
            const float* wrp = wr + (t * DIN) * 128 + j;
            const float* fp = sft + (t * DIN) * PADN + half * 16;
#pragma unroll 8
            for (int d = 0; d < DIN; d++) {
                float ws = wfp[(size_t)d * 128];
                float rs = wrp[(size_t)d * 128];
                ull w2f = pack2(ws, ws);
                ull w2r = pack2(rs, rs);
                const ull* fv = (const ull*)(fp + d * PADN);
#pragma unroll
                for (int p = 0; p < 8; p++) {
                    ull f2 = fv[p];
                    af[p] = fma2(f2, w2f, af[p]);
                    ar[p] = fma2(f2, w2r, ar[p]);
                }
            }
            int c = hb + t * 32;
#pragma unroll
            for (int p = 0; p < 8; p++) {
                elp[p] = fma2(af[p], al2[t], elp[p]);
                erp[p] = fma2(af[p], ar2[t], erp[p]);
                int n = n0 + half * 16 + 2 * p;
                if (n < N) {
                    g_ft[(size_t)n * FDIM + c] = lo2(af[p]);
                    stcs32(out + (size_t)n * FDIM + c, lo2(ar[p]));
                }
                if (n + 1 < N) {
                    g_ft[(size_t)(n + 1) * FDIM + c] = hi2(af[p]);
                    stcs32(out + (size_t)(n + 1) * FDIM + c, hi2(ar[p]));
                }
            }
        }
        // reduce el/er over the 32 lanes (one head per warp)
#pragma unroll
        for (int p = 0; p < 8; p++) {
            float e0 = lo2(elp[p]), e1 = hi2(elp[p]);
            float r0 = lo2(erp[p]), r1 = hi2(erp[p]);
#pragma unroll
            for (int d = 16; d; d >>= 1) {
                e0 += __shfl_xor_sync(0xffffffffu, e0, d);
                e1 += __shfl_xor_sync(0xffffffffu, e1, d);
                r0 += __shfl_xor_sync(0xffffffffu, r0, d);
                r1 += __shfl_xor_sync(0xffffffffu, r1, d);
            }
            if (lane == 0) {
                int n = n0 + half * 16 + 2 * p;
                if (n < N) { g_el[n * 4 + h] = e0; g_er[n * 4 + h] = r0; }
                if (n + 1 < N) { g_el[(n + 1) * 4 + h] = e1; g_er[(n + 1) * 4 + h] = r1; }
            }
        }
    }
}

// ---------------------------------------------------------------------------
// k7: softmax + aggregation. One warp per dst node; smem-staged (src, weight),
// gather loop unrolled x4. out RMW fully streaming to protect g_ft L2 residency.
// ---------------------------------------------------------------------------
__global__ void __launch_bounds__(256) k7_agg(const int* __restrict__ src,
                                              const int* __restrict__ efeat,
                                              float* __restrict__ out, int N) {
    __shared__ int ssm[8][128];
    __shared__ float4 wsm[8][128];
    int wl = threadIdx.x >> 5;
    int n = (blockIdx.x * blockDim.x + threadIdx.x) >> 5;
    int lane = threadIdx.x & 31;
    if (n >= N) return;
    int s0 = g_off[n];
    int deg = g_off[n + 1] - s0;
    if (deg == 0) return;

    float4 er4 = *(const float4*)(g_er + n * 4);

    float4 vc[4];
    int sc[4];
    float4 m = make_float4(-1e30f, -1e30f, -1e30f, -1e30f);
#pragma unroll
    for (int c = 0; c < 4; c++) {
        int k = lane + 32 * c;
        sc[c] = 0;
        vc[c] = make_float4(0.f, 0.f, 0.f, 0.f);
        if (k < deg) {
            int e = g_eidx[s0 + k];
            int s = src[e];
            int et = efeat[e];
            float4 l4 = *(const float4*)(g_el + s * 4);
            float4 e4 = *(const float4*)(g_ee + et * 4);
            float4 v;
            v.x = lrelu(l4.x + er4.x + e4.x);
            v.y = lrelu(l4.y + er4.y + e4.y);
            v.z = lrelu(l4.z + er4.z + e4.z);
            v.w = lrelu(l4.w + er4.w + e4.w);
            sc[c] = s;
            vc[c] = v;
            m.x = fmaxf(m.x, v.x); m.y = fmaxf(m.y, v.y);
            m.z = fmaxf(m.z, v.z); m.w = fmaxf(m.w, v.w);
        }
    }
    for (int k = lane + 128; k < deg; k += 32) {
        int e = g_eidx[s0 + k];
        int s = src[e];
        int et = efeat[e];
        float4 l4 = *(const float4*)(g_el + s * 4);
        float4 e4 = *(const float4*)(g_ee + et * 4);
        m.x = fmaxf(m.x, lrelu(l4.x + er4.x + e4.x));
        m.y = fmaxf(m.y, lrelu(l4.y + er4.y + e4.y));
        m.z = fmaxf(m.z, lrelu(l4.z + er4.z + e4.z));
        m.w = fmaxf(m.w, lrelu(l4.w + er4.w + e4.w));
    }
#pragma unroll
    for (int d = 16; d; d >>= 1) {
        m.x = fmaxf(m.x, __shfl_xor_sync(0xffffffffu, m.x, d));
        m.y = fmaxf(m.y, __shfl_xor_sync(0xffffffffu, m.y, d));
        m.z = fmaxf(m.z, __shfl_xor_sync(0xffffffffu, m.z, d));
        m.w = fmaxf(m.w, __shfl_xor_sync(0xffffffffu, m.w, d));
    }

    float4 ss = make_float4(0.f, 0.f, 0.f, 0.f);
#pragma unroll
    for (int c = 0; c < 4; c++) {
        int k = lane + 32 * c;
        if (k < deg) {
            float4 ex;
            ex.x = __expf(vc[c].x - m.x);
            ex.y = __expf(vc[c].y - m.y);
            ex.z = __expf(vc[c].z - m.z);
            ex.w = __expf(vc[c].w - m.w);
            vc[c] = ex;
            ss.x += ex.x; ss.y += ex.y; ss.z += ex.z; ss.w += ex.w;
        }
    }
    for (int k = lane + 128; k < deg; k += 32) {
        int e = g_eidx[s0 + k];
        int s = src[e];
        int et = efeat[e];
        float4 l4 = *(const float4*)(g_el + s * 4);
        float4 e4 = *(const float4*)(g_ee + et * 4);
        ss.x += __expf(lrelu(l4.x + er4.x + e4.x) - m.x);
        ss.y += __expf(lrelu(l4.y + er4.y + e4.y) - m.y);
        ss.z += __expf(lrelu(l4.z + er4.z + e4.z) - m.z);
        ss.w += __expf(lrelu(l4.w + er4.w + e4.w) - m.w);
    }
#pragma unroll
    for (int d = 16; d; d >>= 1) {
        ss.x += __shfl_xor_sync(0xffffffffu, ss.x, d);
        ss.y += __shfl_xor_sync(0xffffffffu, ss.y, d);
        ss.z += __shfl_xor_sync(0xffffffffu, ss.z, d);
        ss.w += __shfl_xor_sync(0xffffffffu, ss.w, d);
    }
    float4 invd = make_float4(1.f / ss.x, 1.f / ss.y, 1.f / ss.z, 1.f / ss.w);

#pragma unroll
    for (int c = 0; c < 4; c++) {
        int k = lane + 32 * c;
        if (k < deg && k < 128) {
            ssm[wl][k] = sc[c];
            wsm[wl][k] = make_float4(vc[c].x * invd.x, vc[c].y * invd.y,
                                     vc[c].z * invd.z, vc[c].w * invd.w);
        }
    }
    __syncwarp();

    int h0 = (lane * 4) / 96;
    int h1 = (128 + lane * 4) / 96;
    int h2 = (256 + lane * 4) / 96;

    float4 a0 = make_float4(0.f, 0.f, 0.f, 0.f), a1 = a0, a2 = a0;
    int total = min(deg, 128);
    int k = 0;
    for (; k + 4 <= total; k += 4) {
        int s_[4];
        float4 w_[4];
#pragma unroll
        for (int u = 0; u < 4; u++) { s_[u] = ssm[wl][k + u]; w_[u] = wsm[wl][k + u]; }
        float4 p[4][3];
#pragma unroll
        for (int u = 0; u < 4; u++) {
            const float4* f4 = (const float4*)(g_ft + (size_t)s_[u] * FDIM);
            p[u][0] = f4[lane];
            p[u][1] = f4[32 + lane];
            p[u][2] = f4[64 + lane];
        }
#pragma unroll
        for (int u = 0; u < 4; u++) {
            float w0 = pick4(w_[u], h0), w1 = pick4(w_[u], h1), w2 = pick4(w_[u], h2);
            a0.x += p[u][0].x * w0; a0.y += p[u][0].y * w0; a0.z += p[u][0].z * w0; a0.w += p[u][0].w * w0;
            a1.x += p[u][1].x * w1; a1.y += p[u][1].y * w1; a1.z += p[u][1].z * w1; a1.w += p[u][1].w * w1;
            a2.x += p[u][2].x * w2; a2.y += p[u][2].y * w2; a2.z += p[u][2].z * w2; a2.w += p[u][2].w * w2;
        }
    }
    for (; k < total; k++) {
        int s = ssm[wl][k];
        float4 w4 = wsm[wl][k];
        float w0 = pick4(w4, h0), w1 = pick4(w4, h1), w2 = pick4(w4, h2);
        const float4* f4 = (const float4*)(g_ft + (size_t)s * FDIM);
        float4 p0 = f4[lane], p1 = f4[32 + lane], p2 = f4[64 + lane];
        a0.x += p0.x * w0; a0.y += p0.y * w0; a0.z += p0.z * w0; a0.w += p0.w * w0;
        a1.x += p1.x * w1; a1.y += p1.y * w1; a1.z += p1.z * w1; a1.w += p1.w * w1;
        a2.x += p2.x * w2; a2.y += p2.y * w2; a2.z += p2.z * w2; a2.w += p2.w * w2;
    }
    for (int kk = 128; kk < deg; kk++) {
        int e = g_eidx[s0 + kk];
        int s = src[e];
        int et = efeat[e];
        float4 l4 = *(const float4*)(g_el + s * 4);
        float4 e4 = *(const float4*)(g_ee + et * 4);
        float4 exv;
        exv.x = __expf(lrelu(l4.x + er4.x + e4.x) - m.x) * invd.x;
        exv.y = __expf(lrelu(l4.y + er4.y + e4.y) - m.y) * invd.y;
        exv.z = __expf(lrelu(l4.z + er4.z + e4.z) - m.z) * invd.z;
        exv.w = __expf(lrelu(l4.w + er4.w + e4.w) - m.w) * invd.w;
        float w0 = pick4(exv, h0), w1 = pick4(exv, h1), w2 = pick4(exv, h2);
        const float4* f4 = (const float4*)(g_ft + (size_t)s * FDIM);
        float4 p0 = f4[lane], p1 = f4[32 + lane], p2 = f4[64 + lane];
        a0.x += p0.x * w0; a0.y += p0.y * w0; a0.z += p0.z * w0; a0.w += p0.w * w0;
        a1.x += p1.x * w1; a1.y += p1.y * w1; a1.z += p1.z * w1; a1.w += p1.w * w1;
        a2.x += p2.x * w2; a2.y += p2.y * w2; a2.z += p2.z * w2; a2.w += p2.w * w2;
    }

    float4* o4 = (float4*)(out + (size_t)n * FDIM);
    float4 q;
    q = __ldcs(o4 + lane);
    q.x += a0.x; q.y += a0.y; q.z += a0.z; q.w += a0.w;
    __stcs(o4 + lane, q);
    q = __ldcs(o4 + 32 + lane);
    q.x += a1.x; q.y += a1.y; q.z += a1.z; q.w += a1.w;
    __stcs(o4 + 32 + lane, q);
    q = __ldcs(o4 + 64 + lane);
    q.x += a2.x; q.y += a2.y; q.z += a2.z; q.w += a2.w;
    __stcs(o4 + 64 + lane, q);
}

// ---------------------------------------------------------------------------
extern "C" void kernel_launch(void* const* d_in, const int* in_sizes, int n_in,
                              void* d_out, int out_size) {
    const float* feat   = (const float*)d_in[0];
    const int*   e_feat = (const int*)d_in[1];
    const int*   src    = (const int*)d_in[2];
    const int*   dst    = (const int*)d_in[3];
    const float* fc     = (const float*)d_in[4];
    const float* resw   = (const float*)d_in[5];
    const float* emb    = (const float*)d_in[6];
    const float* fce    = (const float*)d_in[7];
    const float* attn_l = (const float*)d_in[8];
    const float* attn_r = (const float*)d_in[9];
    const float* attn_e = (const float*)d_in[10];
    float* out = (float*)d_out;

    int N = in_sizes[0] / FEAT_IN;
    int E = in_sizes[1];

    cudaFuncSetAttribute(k1_transform, cudaFuncAttributeMaxDynamicSharedMemorySize,
                         K1_SMEM_FLOATS * (int)sizeof(float));

    int scanBlocks = (N + 1 + 511) / 512;

    // launch order chosen so k1 is the 4th launch (ncu captures launch #4)
    k_zero<<<(N + 256) / 256, 256>>>(N);
    k_count<<<(E / 4 + 255) / 256, 256>>>(dst, E);
    k_scan1<<<scanBlocks, 512>>>(N);
    k1_transform<<<148, 256, K1_SMEM_FLOATS * (int)sizeof(float)>>>(
        feat, fc, resw, attn_l, attn_r, out, N);
    k_scan2<<<1, 256>>>(scanBlocks);
    k_scan3<<<scanBlocks, 512>>>(N);
    k_scatter<<<(E / 4 + 255) / 256, 256>>>(dst, E);
    k_ee<<<1, 640>>>(emb, fce, attn_e);
    k7_agg<<<(N + 7) / 8, 256>>>(src, e_feat, out, N);
}

// round 4
// speedup vs baseline: 1.4994x; 1.0412x over previous
#include <cuda_runtime.h>

#define T_ 3
#define H_ 4
#define DIN 64
#define FEAT_IN 192     /* T_*DIN */
#define FDIM 384        /* H_ * T_*32 */
#define EF_ 64
#define NET 5
#define MAXN 50000
#define MAXE 400000
#define NEG_SLOPE 0.2f
#define PADN 36

typedef unsigned long long ull;

__device__ float g_ft[(size_t)MAXN * FDIM];
__device__ float g_el[MAXN * H_];
__device__ float g_er[MAXN * H_];
__device__ float g_ee[32];
__device__ int   g_cnt[MAXN + 1];
__device__ int   g_off[MAXN + 1];
__device__ int   g_cur[MAXN + 1];
__device__ int   g_eidx[MAXE];
__device__ int   g_part[256];

__device__ __forceinline__ ull pack2(float x, float y) {
    ull r; asm("mov.b64 %0, {%1,%2};" : "=l"(r) : "f"(x), "f"(y)); return r;
}
__device__ __forceinline__ ull fma2(ull a, ull b, ull c) {
    ull d; asm("fma.rn.f32x2 %0, %1, %2, %3;" : "=l"(d) : "l"(a), "l"(b), "l"(c)); return d;
}
__device__ __forceinline__ float lo2(ull v) { return __uint_as_float((unsigned)(v & 0xffffffffull)); }
__device__ __forceinline__ float hi2(ull v) { return __uint_as_float((unsigned)(v >> 32)); }
__device__ __forceinline__ void stcs32(float* p, float v) {
    asm volatile("st.global.cs.f32 [%0], %1;" :: "l"(p), "f"(v) : "memory");
}
__device__ __forceinline__ float lrelu(float x) { return x >= 0.f ? x : NEG_SLOPE * x; }
__device__ __forceinline__ float pick4(float4 v, int h) {
    float r = v.x;
    r = (h == 1) ? v.y : r;
    r = (h == 2) ? v.z : r;
    r = (h == 3) ? v.w : r;
    return r;
}

// ---------------------------------------------------------------------------
// CSR build
// ---------------------------------------------------------------------------
__global__ void k_zero(int N) {
    int i = blockIdx.x * blockDim.x + threadIdx.x;
    if (i <= N) g_cnt[i] = 0;
}

__global__ void k_count(const int* __restrict__ dst, int E) {
    int i = blockIdx.x * blockDim.x + threadIdx.x;
    int base = i * 4;
    if (base + 3 < E) {
        int4 d = *(const int4*)(dst + base);
        atomicAdd(&g_cnt[d.x], 1);
        atomicAdd(&g_cnt[d.y], 1);
        atomicAdd(&g_cnt[d.z], 1);
        atomicAdd(&g_cnt[d.w], 1);
    } else {
        for (int e = base; e < E; e++) atomicAdd(&g_cnt[dst[e]], 1);
    }
}

__global__ void k_scan1(int N) {
    __shared__ int wsum[16];
    int t = threadIdx.x;
    int idx = blockIdx.x * 512 + t;
    int lane = t & 31, w = t >> 5;
    int x = (idx <= N) ? g_cnt[idx] : 0;
    int incl = x;
#pragma unroll
    for (int d = 1; d < 32; d <<= 1) {
        int y = __shfl_up_sync(0xffffffffu, incl, d);
        if (lane >= d) incl += y;
    }
    if (lane == 31) wsum[w] = incl;
    __syncthreads();
    if (t < 32) {
        int s = (t < 16) ? wsum[t] : 0;
#pragma unroll
        for (int d = 1; d < 16; d <<= 1) {
            int y = __shfl_up_sync(0xffffffffu, s, d);
            if (t >= d) s += y;
        }
        if (t < 16) wsum[t] = s;
    }
    __syncthreads();
    int excl = (w ? wsum[w - 1] : 0) + incl - x;
    if (idx <= N) g_off[idx] = excl;
    if (t == 0) g_part[blockIdx.x] = wsum[15];
}

__global__ void k_scan2(int P) {
    __shared__ int sm[256];
    int t = threadIdx.x;
    int v = (t < P) ? g_part[t] : 0;
    sm[t] = v;
    __syncthreads();
    for (int d = 1; d < 256; d <<= 1) {
        int y = (t >= d) ? sm[t - d] : 0;
        __syncthreads();
        sm[t] += y;
        __syncthreads();
    }
    if (t < P) g_part[t] = sm[t] - v;  // exclusive
}

__global__ void k_scan3(int N) {
    int idx = blockIdx.x * 512 + threadIdx.x;
    if (idx <= N) {
        int o = g_off[idx] + g_part[blockIdx.x];
        g_off[idx] = o;
        g_cur[idx] = o;
    }
}

__global__ void k_scatter(const int* __restrict__ dst, int E) {
    int i = blockIdx.x * blockDim.x + threadIdx.x;
    int base = i * 4;
    if (base + 3 < E) {
        int4 d = *(const int4*)(dst + base);
        int p0 = atomicAdd(&g_cur[d.x], 1);
        int p1 = atomicAdd(&g_cur[d.y], 1);
        int p2 = atomicAdd(&g_cur[d.z], 1);
        int p3 = atomicAdd(&g_cur[d.w], 1);
        g_eidx[p0] = base;
        g_eidx[p1] = base + 1;
        g_eidx[p2] = base + 2;
        g_eidx[p3] = base + 3;
    } else {
        for (int e = base; e < E; e++) {
            int p = atomicAdd(&g_cur[dst[e]], 1);
            g_eidx[p] = e;
        }
    }
}

// ---------------------------------------------------------------------------
// ee table
// ---------------------------------------------------------------------------
__global__ void k_ee(const float* __restrict__ emb, const float* __restrict__ fce,
                     const float* __restrict__ attn_e) {
    int w = threadIdx.x >> 5;
    int lane = threadIdx.x & 31;
    if (w >= NET * H_) return;
    int et = w / H_, h = w % H_;
    float acc = 0.f;
    for (int f = lane; f < EF_; f += 32) {
        const float* row = fce + (h * EF_ + f) * EF_;
        float inner = 0.f;
#pragma unroll 8
        for (int k = 0; k < EF_; k++) inner += emb[et * EF_ + k] * row[k];
        acc += inner * attn_e[h * EF_ + f];
    }
#pragma unroll
    for (int d = 16; d; d >>= 1) acc += __shfl_xor_sync(0xffffffffu, acc, d);
    if (lane == 0) g_ee[et * H_ + h] = acc;
}

// ---------------------------------------------------------------------------
// k1: node transform + fused el/er. f32x2 packs NODE PAIRS; feat tile stored
// transposed in SMEM. 512 threads: 128 columns x 4 node-quarters (4 pairs ea).
// 16 warps/SM to hide LDS + FMA latency.
// ---------------------------------------------------------------------------
#define K1_SMEM_FLOATS (2 * T_ * DIN * 128 + T_ * DIN * PADN)  /* 56064 = 224256 B */
__global__ void __launch_bounds__(512) k1_transform(
    const float* __restrict__ feat, const float* __restrict__ fc,
    const float* __restrict__ resw, const float* __restrict__ attn_l,
    const float* __restrict__ attn_r, float* __restrict__ out, int N) {
    extern __shared__ float sh[];
    float* wf = sh;                          // [t*64+d][128]
    float* wr = sh + T_ * DIN * 128;
    float* sft = sh + 2 * T_ * DIN * 128;    // [t*64+d][PADN]
    for (int i = threadIdx.x; i < T_ * DIN * 128; i += blockDim.x) {
        wf[i] = fc[i];
        wr[i] = resw[i];
    }
    int lane = threadIdx.x & 31;
    int h = (threadIdx.x >> 5) & 3;          // head (column block of 32)
    int q = threadIdx.x >> 7;                // node quarter: 8 nodes
    int j = h * 32 + lane;                   // output column within 128
    int hb = h * 96 + lane;                  // output column in FDIM layout

    ull al2[T_], ar2[T_];
#pragma unroll
    for (int t = 0; t < T_; t++) {
        float a = attn_l[hb + t * 32];
        float b = attn_r[hb + t * 32];
        al2[t] = pack2(a, a);
        ar2[t] = pack2(b, b);
    }
    __syncthreads();

    for (int n0 = blockIdx.x * 32; n0 < N; n0 += gridDim.x * 32) {
        __syncthreads();
        int nNodes = min(32, N - n0);
        // transposed tile load: sft[k][n] = feat[n0+n][k]
        for (int i = threadIdx.x; i < 32 * 48; i += 512) {
            int n = i / 48, qq = i % 48;
            float4 v = (n < nNodes)
                ? __ldcs((const float4*)(feat + (size_t)(n0 + n) * FEAT_IN) + qq)
                : make_float4(0.f, 0.f, 0.f, 0.f);
            int k = qq * 4;
            sft[(k + 0) * PADN + n] = v.x;
            sft[(k + 1) * PADN + n] = v.y;
            sft[(k + 2) * PADN + n] = v.z;
            sft[(k + 3) * PADN + n] = v.w;
        }
        __syncthreads();

        ull elp[4], erp[4];
#pragma unroll
        for (int p = 0; p < 4; p++) { elp[p] = 0ull; erp[p] = 0ull; }

#pragma unroll
        for (int t = 0; t < T_; t++) {
            ull af[4], ar[4];
#pragma unroll
            for (int p = 0; p < 4; p++) { af[p] = 0ull; ar[p] = 0ull; }
            const float* wfp = wf + (t * DIN) * 128 + j;
            const float* wrp = wr + (t * DIN) * 128 + j;
            const float* fp = sft + (t * DIN) * PADN + q * 8;
#pragma unroll 8
            for (int d = 0; d < DIN; d++) {
                float ws = wfp[(size_t)d * 128];
                float rs = wrp[(size_t)d * 128];
                ull w2f = pack2(ws, ws);
                ull w2r = pack2(rs, rs);
                const ull* fv = (const ull*)(fp + d * PADN);
#pragma unroll
                for (int p = 0; p < 4; p++) {
                    ull f2 = fv[p];
                    af[p] = fma2(f2, w2f, af[p]);
                    ar[p] = fma2(f2, w2r, ar[p]);
                }
            }
            int c = hb + t * 32;
#pragma unroll
            for (int p = 0; p < 4; p++) {
                elp[p] = fma2(af[p], al2[t], elp[p]);
                erp[p] = fma2(af[p], ar2[t], erp[p]);
                int n = n0 + q * 8 + 2 * p;
                if (n < N) {
                    g_ft[(size_t)n * FDIM + c] = lo2(af[p]);
                    stcs32(out + (size_t)n * FDIM + c, lo2(ar[p]));
                }
                if (n + 1 < N) {
                    g_ft[(size_t)(n + 1) * FDIM + c] = hi2(af[p]);
                    stcs32(out + (size_t)(n + 1) * FDIM + c, hi2(ar[p]));
                }
            }
        }
        // reduce el/er over the 32 lanes (one head per warp)
#pragma unroll
        for (int p = 0; p < 4; p++) {
            float e0 = lo2(elp[p]), e1 = hi2(elp[p]);
            float r0 = lo2(erp[p]), r1 = hi2(erp[p]);
#pragma unroll
            for (int d = 16; d; d >>= 1) {
                e0 += __shfl_xor_sync(0xffffffffu, e0, d);
                e1 += __shfl_xor_sync(0xffffffffu, e1, d);
                r0 += __shfl_xor_sync(0xffffffffu, r0, d);
                r1 += __shfl_xor_sync(0xffffffffu, r1, d);
            }
            if (lane == 0) {
                int n = n0 + q * 8 + 2 * p;
                if (n < N) { g_el[n * 4 + h] = e0; g_er[n * 4 + h] = r0; }
                if (n + 1 < N) { g_el[(n + 1) * 4 + h] = e1; g_er[(n + 1) * 4 + h] = r1; }
            }
        }
    }
}

// ---------------------------------------------------------------------------
// k7: softmax + aggregation. One warp per dst node; smem-staged (src, weight),
// gather loop unrolled x4. out RMW fully streaming to protect g_ft L2 residency.
// ---------------------------------------------------------------------------
__global__ void __launch_bounds__(256) k7_agg(const int* __restrict__ src,
                                              const int* __restrict__ efeat,
                                              float* __restrict__ out, int N) {
    __shared__ int ssm[8][128];
    __shared__ float4 wsm[8][128];
    int wl = threadIdx.x >> 5;
    int n = (blockIdx.x * blockDim.x + threadIdx.x) >> 5;
    int lane = threadIdx.x & 31;
    if (n >= N) return;
    int s0 = g_off[n];
    int deg = g_off[n + 1] - s0;
    if (deg == 0) return;

    float4 er4 = *(const float4*)(g_er + n * 4);

    float4 vc[4];
    int sc[4];
    float4 m = make_float4(-1e30f, -1e30f, -1e30f, -1e30f);
#pragma unroll
    for (int c = 0; c < 4; c++) {
        int k = lane + 32 * c;
        sc[c] = 0;
        vc[c] = make_float4(0.f, 0.f, 0.f, 0.f);
        if (k < deg) {
            int e = g_eidx[s0 + k];
            int s = src[e];
            int et = efeat[e];
            float4 l4 = *(const float4*)(g_el + s * 4);
            float4 e4 = *(const float4*)(g_ee + et * 4);
            float4 v;
            v.x = lrelu(l4.x + er4.x + e4.x);
            v.y = lrelu(l4.y + er4.y + e4.y);
            v.z = lrelu(l4.z + er4.z + e4.z);
            v.w = lrelu(l4.w + er4.w + e4.w);
            sc[c] = s;
            vc[c] = v;
            m.x = fmaxf(m.x, v.x); m.y = fmaxf(m.y, v.y);
            m.z = fmaxf(m.z, v.z); m.w = fmaxf(m.w, v.w);
        }
    }
    for (int k = lane + 128; k < deg; k += 32) {
        int e = g_eidx[s0 + k];
        int s = src[e];
        int et = efeat[e];
        float4 l4 = *(const float4*)(g_el + s * 4);
        float4 e4 = *(const float4*)(g_ee + et * 4);
        m.x = fmaxf(m.x, lrelu(l4.x + er4.x + e4.x));
        m.y = fmaxf(m.y, lrelu(l4.y + er4.y + e4.y));
        m.z = fmaxf(m.z, lrelu(l4.z + er4.z + e4.z));
        m.w = fmaxf(m.w, lrelu(l4.w + er4.w + e4.w));
    }
#pragma unroll
    for (int d = 16; d; d >>= 1) {
        m.x = fmaxf(m.x, __shfl_xor_sync(0xffffffffu, m.x, d));
        m.y = fmaxf(m.y, __shfl_xor_sync(0xffffffffu, m.y, d));
        m.z = fmaxf(m.z, __shfl_xor_sync(0xffffffffu, m.z, d));
        m.w = fmaxf(m.w, __shfl_xor_sync(0xffffffffu, m.w, d));
    }

    float4 ss = make_float4(0.f, 0.f, 0.f, 0.f);
#pragma unroll
    for (int c = 0; c < 4; c++) {
        int k = lane + 32 * c;
        if (k < deg) {
            float4 ex;
            ex.x = __expf(vc[c].x - m.x);
            ex.y = __expf(vc[c].y - m.y);
            ex.z = __expf(vc[c].z - m.z);
            ex.w = __expf(vc[c].w - m.w);
            vc[c] = ex;
            ss.x += ex.x; ss.y += ex.y; ss.z += ex.z; ss.w += ex.w;
        }
    }
    for (int k = lane + 128; k < deg; k += 32) {
        int e = g_eidx[s0 + k];
        int s = src[e];
        int et = efeat[e];
        float4 l4 = *(const float4*)(g_el + s * 4);
        float4 e4 = *(const float4*)(g_ee + et * 4);
        ss.x += __expf(lrelu(l4.x + er4.x + e4.x) - m.x);
        ss.y += __expf(lrelu(l4.y + er4.y + e4.y) - m.y);
        ss.z += __expf(lrelu(l4.z + er4.z + e4.z) - m.z);
        ss.w += __expf(lrelu(l4.w + er4.w + e4.w) - m.w);
    }
#pragma unroll
    for (int d = 16; d; d >>= 1) {
        ss.x += __shfl_xor_sync(0xffffffffu, ss.x, d);
        ss.y += __shfl_xor_sync(0xffffffffu, ss.y, d);
        ss.z += __shfl_xor_sync(0xffffffffu, ss.z, d);
        ss.w += __shfl_xor_sync(0xffffffffu, ss.w, d);
    }
    float4 invd = make_float4(1.f / ss.x, 1.f / ss.y, 1.f / ss.z, 1.f / ss.w);

#pragma unroll
    for (int c = 0; c < 4; c++) {
        int k = lane + 32 * c;
        if (k < deg && k < 128) {
            ssm[wl][k] = sc[c];
            wsm[wl][k] = make_float4(vc[c].x * invd.x, vc[c].y * invd.y,
                                     vc[c].z * invd.z, vc[c].w * invd.w);
        }
    }
    __syncwarp();

    int h0 = (lane * 4) / 96;
    int h1 = (128 + lane * 4) / 96;
    int h2 = (256 + lane * 4) / 96;

    float4 a0 = make_float4(0.f, 0.f, 0.f, 0.f), a1 = a0, a2 = a0;
    int total = min(deg, 128);
    int k = 0;
    for (; k + 4 <= total; k += 4) {
        int s_[4];
        float4 w_[4];
#pragma unroll
        for (int u = 0; u < 4; u++) { s_[u] = ssm[wl][k + u]; w_[u] = wsm[wl][k + u]; }
        float4 p[4][3];
#pragma unroll
        for (int u = 0; u < 4; u++) {
            const float4* f4 = (const float4*)(g_ft + (size_t)s_[u] * FDIM);
            p[u][0] = f4[lane];
            p[u][1] = f4[32 + lane];
            p[u][2] = f4[64 + lane];
        }
#pragma unroll
        for (int u = 0; u < 4; u++) {
            float w0 = pick4(w_[u], h0), w1 = pick4(w_[u], h1), w2 = pick4(w_[u], h2);
            a0.x += p[u][0].x * w0; a0.y += p[u][0].y * w0; a0.z += p[u][0].z * w0; a0.w += p[u][0].w * w0;
            a1.x += p[u][1].x * w1; a1.y += p[u][1].y * w1; a1.z += p[u][1].z * w1; a1.w += p[u][1].w * w1;
            a2.x += p[u][2].x * w2; a2.y += p[u][2].y * w2; a2.z += p[u][2].z * w2; a2.w += p[u][2].w * w2;
        }
    }
    for (; k < total; k++) {
        int s = ssm[wl][k];
        float4 w4 = wsm[wl][k];
        float w0 = pick4(w4, h0), w1 = pick4(w4, h1), w2 = pick4(w4, h2);
        const float4* f4 = (const float4*)(g_ft + (size_t)s * FDIM);
        float4 p0 = f4[lane], p1 = f4[32 + lane], p2 = f4[64 + lane];
        a0.x += p0.x * w0; a0.y += p0.y * w0; a0.z += p0.z * w0; a0.w += p0.w * w0;
        a1.x += p1.x * w1; a1.y += p1.y * w1; a1.z += p1.z * w1; a1.w += p1.w * w1;
        a2.x += p2.x * w2; a2.y += p2.y * w2; a2.z += p2.z * w2; a2.w += p2.w * w2;
    }
    for (int kk = 128; kk < deg; kk++) {
        int e = g_eidx[s0 + kk];
        int s = src[e];
        int et = efeat[e];
        float4 l4 = *(const float4*)(g_el + s * 4);
        float4 e4 = *(const float4*)(g_ee + et * 4);
        float4 exv;
        exv.x = __expf(lrelu(l4.x + er4.x + e4.x) - m.x) * invd.x;
        exv.y = __expf(lrelu(l4.y + er4.y + e4.y) - m.y) * invd.y;
        exv.z = __expf(lrelu(l4.z + er4.z + e4.z) - m.z) * invd.z;
        exv.w = __expf(lrelu(l4.w + er4.w + e4.w) - m.w) * invd.w;
        float w0 = pick4(exv, h0), w1 = pick4(exv, h1), w2 = pick4(exv, h2);
        const float4* f4 = (const float4*)(g_ft + (size_t)s * FDIM);
        float4 p0 = f4[lane], p1 = f4[32 + lane], p2 = f4[64 + lane];
        a0.x += p0.x * w0; a0.y += p0.y * w0; a0.z += p0.z * w0; a0.w += p0.w * w0;
        a1.x += p1.x * w1; a1.y += p1.y * w1; a1.z += p1.z * w1; a1.w += p1.w * w1;
        a2.x += p2.x * w2; a2.y += p2.y * w2; a2.z += p2.z * w2; a2.w += p2.w * w2;
    }

    float4* o4 = (float4*)(out + (size_t)n * FDIM);
    float4 q;
    q = __ldcs(o4 + lane);
    q.x += a0.x; q.y += a0.y; q.z += a0.z; q.w += a0.w;
    __stcs(o4 + lane, q);
    q = __ldcs(o4 + 32 + lane);
    q.x += a1.x; q.y += a1.y; q.z += a1.z; q.w += a1.w;
    __stcs(o4 + 32 + lane, q);
    q = __ldcs(o4 + 64 + lane);
    q.x += a2.x; q.y += a2.y; q.z += a2.z; q.w += a2.w;
    __stcs(o4 + 64 + lane, q);
}

// ---------------------------------------------------------------------------
extern "C" void kernel_launch(void* const* d_in, const int* in_sizes, int n_in,
                              void* d_out, int out_size) {
    const float* feat   = (const float*)d_in[0];
    const int*   e_feat = (const int*)d_in[1];
    const int*   src    = (const int*)d_in[2];
    const int*   dst    = (const int*)d_in[3];
    const float* fc     = (const float*)d_in[4];
    const float* resw   = (const float*)d_in[5];
    const float* emb    = (const float*)d_in[6];
    const float* fce    = (const float*)d_in[7];
    const float* attn_l = (const float*)d_in[8];
    const float* attn_r = (const float*)d_in[9];
    const float* attn_e = (const float*)d_in[10];
    float* out = (float*)d_out;

    int N = in_sizes[0] / FEAT_IN;
    int E = in_sizes[1];

    cudaFuncSetAttribute(k1_transform, cudaFuncAttributeMaxDynamicSharedMemorySize,
                         K1_SMEM_FLOATS * (int)sizeof(float));

    int scanBlocks = (N + 1 + 511) / 512;

    // launch order keeps k1 in the profiler's capture slot (4th launch)
    k_zero<<<(N + 256) / 256, 256>>>(N);
    k_count<<<(E / 4 + 255) / 256, 256>>>(dst, E);
    k_scan1<<<scanBlocks, 512>>>(N);
    k1_transform<<<148, 512, K1_SMEM_FLOATS * (int)sizeof(float)>>>(
        feat, fc, resw, attn_l, attn_r, out, N);
    k_scan2<<<1, 256>>>(scanBlocks);
    k_scan3<<<scanBlocks, 512>>>(N);
    k_scatter<<<(E / 4 + 255) / 256, 256>>>(dst, E);
    k_ee<<<1, 640>>>(emb, fce, attn_e);
    k7_agg<<<(N + 7) / 8, 256>>>(src, e_feat, out, N);
}